// round 10
// baseline (speedup 1.0000x reference)
#include <cuda_runtime.h>
#include <cuda_fp16.h>
#include <cstdint>

// ---------------------------------------------------------------------------
// SoftPatternClassifier on GB300 — vocab-compacted 3xFP16 mma.sync GEMM
//   R10: 3-stage cp.async pipeline (1 sync/chunk), scan chunks 32x16,
//        split_emb writes only used tokens.
// ---------------------------------------------------------------------------

#define BDIM 64
#define LDIM 512
#define VDIM 20000
#define PDIM 150
#define CDIM 750
#define KDIM 300
#define NEGF (-1000000000.0f)

#define TSTR 752
#define KPAD 304              // 19 chunks of 16
#define NPAIR (KPAD / 2)      // 152 half2 pairs per row
#define CPAD 768
#define VPAD 20096            // 157 * 128

#define TK 16                 // K values per chunk (8 pairs)
#define NCHUNK (KPAD / TK)    // 19
#define ASTR 12               // smem row stride (floats); payload 8

#define NSC 32                // scan time-chunks
#define SCT 16                // positions per scan chunk

// __device__ scratch (allocation-free rule)
__device__ float   d_table[(size_t)VPAD * TSTR];  // ~60 MB (cid-indexed)
__device__ __half2 d_Ahi[CPAD * NPAIR];
__device__ __half2 d_Alo[CPAD * NPAIR];
__device__ __half2 d_Bhi[(size_t)VPAD * NPAIR];   // ~6.1 MB (token-indexed)
__device__ __half2 d_Blo[(size_t)VPAD * NPAIR];
__device__ float   d_part[BDIM][NSC][160];
__device__ int     d_flag[VDIM];
__device__ int     d_cid[VDIM];                   // token -> compact id (0 if unused)
__device__ int     d_used[VPAD];                  // compact id -> token
__device__ int     d_count;

// ---------------------------------------------------------------------------
// helpers
// ---------------------------------------------------------------------------
__device__ __forceinline__ float logsig(float x) {
    return fminf(x, 0.0f) - log1pf(expf(-fabsf(x)));
}
__device__ __forceinline__ void cpa16(uint32_t dst, const void* src) {
    asm volatile("cp.async.cg.shared.global [%0], [%1], 16;" :: "r"(dst), "l"(src) : "memory");
}
#define CPA_COMMIT() asm volatile("cp.async.commit_group;" ::: "memory")
#define CPA_WAIT1()  asm volatile("cp.async.wait_group 1;" ::: "memory")
#define CPA_WAIT0()  asm volatile("cp.async.wait_group 0;" ::: "memory")

__device__ __forceinline__ uint32_t smem_u32(const void* p) {
    uint32_t a;
    asm("{ .reg .u64 t; cvta.to.shared.u64 t, %1; cvt.u32.u64 %0, t; }" : "=r"(a) : "l"(p));
    return a;
}

// pair-interleave within groups of 8 pairs: stored order (0,4,1,5,2,6,3,7)
__device__ __forceinline__ int pslot(int j) {
    return (j & ~7) + 2 * (j & 3) + ((j >> 2) & 1);
}

__device__ __forceinline__ void mma16816(float* d, uint32_t a0, uint32_t a1,
                                         uint32_t a2, uint32_t a3,
                                         uint32_t b0, uint32_t b1) {
    asm volatile(
        "mma.sync.aligned.m16n8k16.row.col.f32.f16.f16.f32 "
        "{%0,%1,%2,%3}, {%4,%5,%6,%7}, {%8,%9}, {%0,%1,%2,%3};"
        : "+f"(d[0]), "+f"(d[1]), "+f"(d[2]), "+f"(d[3])
        : "r"(a0), "r"(a1), "r"(a2), "r"(a3), "r"(b0), "r"(b1));
}

__device__ __forceinline__ void fp16split(float x, __half& h, __half& l) {
    h = __float2half_rn(x);
    l = __float2half_rn(x - __half2float(h));
}

// ---------------------------------------------------------------------------
// 0a. clear flags / maps / count
// ---------------------------------------------------------------------------
__global__ void clear_kernel() {
    int i = blockIdx.x * blockDim.x + threadIdx.x;
    if (i < VDIM) { d_flag[i] = 0; d_cid[i] = 0; }
    if (i < VPAD) d_used[i] = 0;
    if (i == 0) d_count = 0;
}

// 0b. mark tokens appearing within doc_lens
__global__ void mark_kernel(const int* __restrict__ docs,
                            const int* __restrict__ doc_lens) {
    int i = blockIdx.x * blockDim.x + threadIdx.x;     // over B*L
    int b = i >> 9, t = i & (LDIM - 1);
    if (b < BDIM && t < doc_lens[b]) d_flag[docs[i]] = 1;
}

// 0c. assign compact ids (warp-aggregated atomics)
__global__ void assign_kernel() {
    int v = blockIdx.x * blockDim.x + threadIdx.x;
    if (v >= VDIM) return;
    int lane = threadIdx.x & 31;
    int f = d_flag[v];
    unsigned mask = __ballot_sync(0xffffffffu, f != 0);
    int base = 0;
    if (lane == 0 && mask) base = atomicAdd(&d_count, __popc(mask));
    base = __shfl_sync(0xffffffffu, base, 0);
    if (f) {
        int cid = base + __popc(mask & ((1u << lane) - 1));
        d_cid[v] = cid;
        d_used[cid] = v;
    }
}

// ---------------------------------------------------------------------------
// 1. split diags -> fp16 hi/lo half2 pairs, [CPAD][NPAIR], pair-interleaved
// ---------------------------------------------------------------------------
__global__ void split_diags_kernel(const float* __restrict__ diags) {
    int i = blockIdx.x * blockDim.x + threadIdx.x;
    if (i >= CPAD * NPAIR) return;
    int c = i / NPAIR;
    int j = i - c * NPAIR;
    int k0 = 2 * j, k1 = 2 * j + 1;
    float x0 = 0.0f, x1 = 0.0f;
    if (c < CDIM) {
        int row = (c / 5) * 6 + (c % 5);
        if (k0 < KDIM) x0 = diags[row * KDIM + k0];
        if (k1 < KDIM) x1 = diags[row * KDIM + k1];
    }
    __half h0, l0, h1, l1;
    fp16split(x0, h0, l0);
    fp16split(x1, h1, l1);
    int dst = c * NPAIR + pslot(j);
    d_Ahi[dst] = __halves2half2(h0, h1);
    d_Alo[dst] = __halves2half2(l0, l1);
}

// ---------------------------------------------------------------------------
// 2. transpose+split E -> B_hi/B_lo [VPAD][NPAIR], only USED token rows
// ---------------------------------------------------------------------------
__global__ void split_emb_kernel(const float* __restrict__ E) {
    __shared__ float tile[32][33];
    int vt = blockIdx.x * 32;
    int kt = blockIdx.y * 32;
    int tx = threadIdx.x, ty = threadIdx.y;   // (32, 8)
#pragma unroll
    for (int r = 0; r < 4; r++) {
        int k = kt + ty + r * 8, v = vt + tx;
        tile[ty + r * 8][tx] = (k < KDIM && v < VDIM) ? E[(size_t)k * VDIM + v] : 0.0f;
    }
    __syncthreads();
    int tid = ty * 32 + tx;
#pragma unroll
    for (int w = 0; w < 2; w++) {
        int idx = tid + 256 * w;               // 0..511 = 32 v x 16 pairs
        int j = idx & 15, vv = idx >> 4;
        int gp = (kt >> 1) + j;                // global pair index
        if (gp >= NPAIR) continue;
        int v = vt + vv;
        if (v >= VDIM || !d_flag[v]) continue; // skip unused tokens
        float x0 = tile[2 * j][vv];
        float x1 = tile[2 * j + 1][vv];
        __half h0, l0, h1, l1;
        fp16split(x0, h0, l0);
        fp16split(x1, h1, l1);
        size_t o = (size_t)v * NPAIR + pslot(gp);
        d_Bhi[o] = __halves2half2(h0, h1);
        d_Blo[o] = __halves2half2(l0, l1);
    }
}

// ---------------------------------------------------------------------------
// 3. GEMM over USED tokens only: D[128 cid x 128 c] per CTA.
//    mma.sync m16n8k16 f16, 3x split; 19 k16 chunks, 3-stage cp.async.
// ---------------------------------------------------------------------------
#define ARR_BYTES   (128 * ASTR * 4)           // 6144
#define STAGE_BYTES (4 * ARR_BYTES)            // 24576
#define NSTAGE      3
#define TOK_BYTES   512
#define GSMEM_TOTAL (NSTAGE * STAGE_BYTES + TOK_BYTES)  // 74240
#define OFF_AH 0
#define OFF_AL ARR_BYTES
#define OFF_BH (2 * ARR_BYTES)
#define OFF_BL (3 * ARR_BYTES)

__global__ void __launch_bounds__(256, 2)
gemm_mma_kernel(const float* __restrict__ bias) {
    extern __shared__ __align__(16) char smem[];
    const uint32_t sb = smem_u32(smem);
    int* s_tok = (int*)(smem + NSTAGE * STAGE_BYTES);

    const int cnt = d_count;
    const int vBase = blockIdx.x * 128;        // compact-id base
    if (vBase >= cnt) return;

    const int tid = threadIdx.x;
    const int wid = tid >> 5;
    const int lid = tid & 31;
    const int g   = lid >> 2;
    const int t   = lid & 3;
    const int wm  = (wid & 3) * 32;
    const int wn  = (wid >> 2) * 64;
    const int cBase = blockIdx.y * 128;

    if (tid < 128) {
        int cid = vBase + tid;
        s_tok[tid] = d_used[(cid < cnt) ? cid : 0];
    }
    __syncthreads();

    const __half2* gAh = d_Ahi + (size_t)cBase * NPAIR;   // MMA B operand (n = c)
    const __half2* gAl = d_Alo + (size_t)cBase * NPAIR;

    auto load_chunk = [&](int kc, int s) {
        const uint32_t st = sb + s * STAGE_BYTES;
        const int p0 = kc * 8;                  // first pair of chunk
        int r = tid >> 1, q = (tid & 1) * 4;
        uint32_t so = (uint32_t)(r * ASTR + q) * 4;
        // m rows (cid) gathered via s_tok
        size_t gm = (size_t)s_tok[r] * NPAIR + p0 + q;
        cpa16(st + OFF_AH + so, d_Bhi + gm);
        cpa16(st + OFF_AL + so, d_Blo + gm);
        // n rows (c) dense
        size_t gn = (size_t)r * NPAIR + p0 + q;
        cpa16(st + OFF_BH + so, gAh + gn);
        cpa16(st + OFF_BL + so, gAl + gn);
        CPA_COMMIT();
    };

    float acc[2][8][4];
#pragma unroll
    for (int mi = 0; mi < 2; mi++)
#pragma unroll
        for (int ni = 0; ni < 8; ni++)
#pragma unroll
            for (int e = 0; e < 4; e++) acc[mi][ni][e] = 0.0f;

    load_chunk(0, 0);
    load_chunk(1, 1);

    int s = 0;                                  // stage of chunk i
    for (int i = 0; i < NCHUNK; i++) {
        if (i + 1 < NCHUNK) { CPA_WAIT1(); } else { CPA_WAIT0(); }
        __syncthreads();
        // prefetch chunk i+2 into stage (i+2)%3 == (i-1)%3 (consumed at i-1)
        if (i + 2 < NCHUNK) {
            int s2 = s + 2; if (s2 >= NSTAGE) s2 -= NSTAGE;
            load_chunk(i + 2, s2);
        }

        const float* sAh = (const float*)(smem + s * STAGE_BYTES + OFF_AH);
        const float* sAl = (const float*)(smem + s * STAGE_BYTES + OFF_AL);
        const float* sBh = (const float*)(smem + s * STAGE_BYTES + OFF_BH);
        const float* sBl = (const float*)(smem + s * STAGE_BYTES + OFF_BL);

        const int kcol = 2 * t;                 // pair-slot offset (floats)

        uint32_t Ah[2][4], Al[2][4];
#pragma unroll
        for (int mi = 0; mi < 2; mi++) {
            int r0 = wm + mi * 16 + g;
            float2 h0 = *(const float2*)&sAh[r0 * ASTR + kcol];
            float2 h1 = *(const float2*)&sAh[(r0 + 8) * ASTR + kcol];
            float2 l0 = *(const float2*)&sAl[r0 * ASTR + kcol];
            float2 l1 = *(const float2*)&sAl[(r0 + 8) * ASTR + kcol];
            Ah[mi][0] = __float_as_uint(h0.x); Ah[mi][1] = __float_as_uint(h1.x);
            Ah[mi][2] = __float_as_uint(h0.y); Ah[mi][3] = __float_as_uint(h1.y);
            Al[mi][0] = __float_as_uint(l0.x); Al[mi][1] = __float_as_uint(l1.x);
            Al[mi][2] = __float_as_uint(l0.y); Al[mi][3] = __float_as_uint(l1.y);
        }
#pragma unroll
        for (int ni = 0; ni < 8; ni++) {
            int rn = wn + ni * 8 + g;
            float2 h = *(const float2*)&sBh[rn * ASTR + kcol];
            float2 l = *(const float2*)&sBl[rn * ASTR + kcol];
            uint32_t bh0 = __float_as_uint(h.x), bh1 = __float_as_uint(h.y);
            uint32_t bl0 = __float_as_uint(l.x), bl1 = __float_as_uint(l.y);
#pragma unroll
            for (int mi = 0; mi < 2; mi++) {
                mma16816(acc[mi][ni], Ah[mi][0], Ah[mi][1], Ah[mi][2], Ah[mi][3], bh0, bh1);
                mma16816(acc[mi][ni], Ah[mi][0], Ah[mi][1], Ah[mi][2], Ah[mi][3], bl0, bl1);
                mma16816(acc[mi][ni], Al[mi][0], Al[mi][1], Al[mi][2], Al[mi][3], bh0, bh1);
            }
        }
        if (++s >= NSTAGE) s -= NSTAGE;
    }

    // ---- epilogue: +bias, logsig, float2 stores to table[cid][c] ----
#pragma unroll
    for (int ni = 0; ni < 8; ni++) {
        const int c = cBase + wn + ni * 8 + 2 * t;
        if (c >= CDIM) continue;
        const float b0 = __ldg(&bias[(c / 5) * 6 + (c % 5)]);
        const int c1 = c + 1;
        const float b1 = __ldg(&bias[(c1 / 5) * 6 + (c1 % 5)]);
#pragma unroll
        for (int mi = 0; mi < 2; mi++) {
            const int v0 = vBase + wm + mi * 16 + g;
            const int v1 = v0 + 8;
            if (v0 < cnt) {
                float2 r;
                r.x = logsig(acc[mi][ni][0] + b0);
                r.y = logsig(acc[mi][ni][1] + b1);
                *(float2*)&d_table[(size_t)v0 * TSTR + c] = r;
            }
            if (v1 < cnt) {
                float2 r;
                r.x = logsig(acc[mi][ni][2] + b0);
                r.y = logsig(acc[mi][ni][3] + b1);
                *(float2*)&d_table[(size_t)v1 * TSTR + c] = r;
            }
        }
    }
}

// ---------------------------------------------------------------------------
// 4. chunked scan: block (b, ch) covers positions [ch*16, ch*16+16) with a
//    4-token warmup; tokens remapped to compact ids.
// ---------------------------------------------------------------------------
__global__ void __launch_bounds__(160)
scan_part_kernel(const int*   __restrict__ docs,
                 const int*   __restrict__ doc_lens,
                 const float* __restrict__ wildcards) {
    const int b   = blockIdx.x;
    const int ch  = blockIdx.y;
    const int tid = threadIdx.x;
    const int p   = tid;
    const bool valid = (p < PDIM);

    const int len = doc_lens[b];
    const int c0  = ch * SCT;
    if (len <= c0) {
        if (valid) d_part[b][ch][p] = NEGF;
        return;
    }

    const int warm   = (ch == 0) ? 0 : 4;
    const int tstart = c0 - warm;
    const int nt     = warm + SCT;   // 16 or 20

    __shared__ int s_tok[SCT + 4];
    if (tid < nt) s_tok[tid] = d_cid[docs[b * LDIM + tstart + tid]];
    __syncthreads();

    float wl[5];
#pragma unroll
    for (int m = 0; m < 5; m++)
        wl[m] = valid ? logsig(__ldg(&wildcards[p * 5 + m])) : 0.0f;

    const int endSel = p / 50;
    float h1 = NEGF, h2 = NEGF, h3 = NEGF, h4 = NEGF, h5 = NEGF;
    float sc = NEGF;

    float pf[4][5];
#pragma unroll
    for (int u = 0; u < 4; u++) {
        if (valid && u < nt) {
            const float* row = &d_table[(size_t)s_tok[u] * TSTR + p * 5];
#pragma unroll
            for (int m = 0; m < 5; m++) pf[u][m] = __ldg(&row[m]);
        } else {
#pragma unroll
            for (int m = 0; m < 5; m++) pf[u][m] = 0.0f;
        }
    }

    const int scoreLo = warm;
    const int scoreHi = (len < c0 + SCT ? len : c0 + SCT) - tstart;

    for (int i = 0; i < nt; i += 4) {
#pragma unroll
        for (int u = 0; u < 4; u++) {
            float e0 = fmaxf(pf[u][0], wl[0]);
            float e1 = fmaxf(pf[u][1], wl[1]);
            float e2 = fmaxf(pf[u][2], wl[2]);
            float e3 = fmaxf(pf[u][3], wl[3]);
            float e4 = fmaxf(pf[u][4], wl[4]);
            h5 = h4 + e4;
            h4 = h3 + e3;
            h3 = h2 + e2;
            h2 = h1 + e1;
            h1 = e0;
            float ev = (endSel == 0) ? h3 : ((endSel == 1) ? h4 : h5);
            int li = i + u;
            sc = (li >= scoreLo && li < scoreHi) ? fmaxf(sc, ev) : sc;
            int ni = li + 4;
            if (ni < nt && valid) {
                const float* row = &d_table[(size_t)s_tok[ni] * TSTR + p * 5];
#pragma unroll
                for (int m = 0; m < 5; m++) pf[u][m] = __ldg(&row[m]);
            }
        }
    }

    if (valid) d_part[b][ch][p] = sc;
}

// ---------------------------------------------------------------------------
// 5. final: reduce chunks, exp/LN/heaviside/linear
// ---------------------------------------------------------------------------
__global__ void __launch_bounds__(160)
scan_final_kernel(const float* __restrict__ gamma,
                  const float* __restrict__ beta,
                  const float* __restrict__ W,
                  const float* __restrict__ lb,
                  float*       __restrict__ out) {
    const int b   = blockIdx.x;
    const int tid = threadIdx.x;
    const bool valid = (tid < PDIM);

    __shared__ float sh[192];
    __shared__ float sred[2];

    float sc = NEGF;
    if (valid) {
#pragma unroll
        for (int ch = 0; ch < NSC; ch++) sc = fmaxf(sc, d_part[b][ch][tid]);
    }
    float score = valid ? expf(sc) : 0.0f;

    sh[tid] = score;
    __syncthreads();
    if (tid < 32) {
        float s = 0.0f;
        for (int i = tid; i < PDIM; i += 32) s += sh[i];
#pragma unroll
        for (int o = 16; o > 0; o >>= 1) s += __shfl_down_sync(0xffffffffu, s, o);
        if (tid == 0) sred[0] = s * (1.0f / PDIM);
    }
    __syncthreads();
    const float mu = sred[0];

    float d = score - mu;
    sh[tid] = valid ? d * d : 0.0f;
    __syncthreads();
    if (tid < 32) {
        float s = 0.0f;
        for (int i = tid; i < PDIM; i += 32) s += sh[i];
#pragma unroll
        for (int o = 16; o > 0; o >>= 1) s += __shfl_down_sync(0xffffffffu, s, o);
        if (tid == 0) sred[1] = s * (1.0f / PDIM);
    }
    __syncthreads();
    const float var = sred[1];

    float bin = 0.0f;
    if (valid) {
        float norm = (score - mu) * rsqrtf(var + 1e-5f) * __ldg(&gamma[tid]) + __ldg(&beta[tid]);
        bin = (norm > 0.0f) ? 1.0f : 0.0f;
    }

    sh[tid] = valid ? bin * __ldg(&W[tid]) : 0.0f;
    __syncthreads();
    if (tid < 32) {
        float s = 0.0f;
        for (int i = tid; i < PDIM; i += 32) s += sh[i];
#pragma unroll
        for (int o = 16; o > 0; o >>= 1) s += __shfl_down_sync(0xffffffffu, s, o);
        if (tid == 0) out[b * 2 + 0] = s + __ldg(&lb[0]);
    }
    __syncthreads();
    sh[tid] = valid ? bin * __ldg(&W[PDIM + tid]) : 0.0f;
    __syncthreads();
    if (tid < 32) {
        float s = 0.0f;
        for (int i = tid; i < PDIM; i += 32) s += sh[i];
#pragma unroll
        for (int o = 16; o > 0; o >>= 1) s += __shfl_down_sync(0xffffffffu, s, o);
        if (tid == 0) out[b * 2 + 1] = s + __ldg(&lb[1]);
    }
}

// ---------------------------------------------------------------------------
// launch
// ---------------------------------------------------------------------------
extern "C" void kernel_launch(void* const* d_in, const int* in_sizes, int n_in,
                              void* d_out, int out_size) {
    const int*   docs      = (const int*)  d_in[0];
    const int*   doc_lens  = (const int*)  d_in[1];
    const float* emb       = (const float*)d_in[2];
    const float* diags     = (const float*)d_in[3];
    const float* bias      = (const float*)d_in[4];
    const float* wildcards = (const float*)d_in[5];
    const float* ln_gamma  = (const float*)d_in[6];
    const float* ln_beta   = (const float*)d_in[7];
    const float* linear_w  = (const float*)d_in[8];
    const float* linear_b  = (const float*)d_in[9];
    float*       out       = (float*)d_out;

    (void)in_sizes; (void)n_in; (void)out_size;

    cudaFuncSetAttribute(gemm_mma_kernel,
                         cudaFuncAttributeMaxDynamicSharedMemorySize, GSMEM_TOTAL);

    clear_kernel<<<(VPAD + 255) / 256, 256>>>();
    mark_kernel<<<(BDIM * LDIM + 255) / 256, 256>>>(docs, doc_lens);
    assign_kernel<<<(VDIM + 255) / 256, 256>>>();

    split_diags_kernel<<<(CPAD * NPAIR + 255) / 256, 256>>>(diags);

    dim3 tgrid((VPAD + 31) / 32, (KPAD + 31) / 32);  // (628, 10)
    split_emb_kernel<<<tgrid, dim3(32, 8)>>>(emb);

    dim3 ggrid(VPAD / 128, CPAD / 128);              // (157, 6)
    gemm_mma_kernel<<<ggrid, 256, GSMEM_TOTAL>>>(bias);

    dim3 sgrid(BDIM, NSC);                           // (64, 32)
    scan_part_kernel<<<sgrid, 160>>>(docs, doc_lens, wildcards);

    scan_final_kernel<<<BDIM, 160>>>(ln_gamma, ln_beta, linear_w, linear_b, out);
}

// round 11
// speedup vs baseline: 1.1952x; 1.1952x over previous
#include <cuda_runtime.h>
#include <cuda_fp16.h>
#include <cstdint>

// ---------------------------------------------------------------------------
// SoftPatternClassifier on GB300 — vocab- AND column-compacted 3xFP16 GEMM
//   R11: only columns actually consumed by the scan are computed:
//        pattern p needs m < end(p) (end = 3/4/5)  -> 600 cols, pad 640.
//        GEMM c-blocks 6 -> 5 (-16.6% MMA); reverts R10's neutral changes.
// ---------------------------------------------------------------------------

#define BDIM 64
#define LDIM 512
#define VDIM 20000
#define PDIM 150
#define CDIM 600              // compacted transition columns
#define KDIM 300
#define NEGF (-1000000000.0f)

#define TSTR 640              // table row stride (= CPAD)
#define KPAD 304              // 19 chunks of 16
#define NPAIR (KPAD / 2)      // 152 half2 pairs per row
#define CPAD 640              // 5 * 128
#define VPAD 20096            // 157 * 128

#define TK 16                 // K values per chunk (8 pairs)
#define NCHUNK (KPAD / TK)    // 19
#define ASTR 12               // smem row stride (floats); payload 8

#define NSC 16                // scan time-chunks
#define SCT 32                // positions per scan chunk

// __device__ scratch (allocation-free rule)
__device__ float   d_table[(size_t)VPAD * TSTR];  // ~51 MB (cid-indexed)
__device__ __half2 d_Ahi[CPAD * NPAIR];
__device__ __half2 d_Alo[CPAD * NPAIR];
__device__ __half2 d_Bhi[(size_t)VPAD * NPAIR];   // ~6.1 MB (token-indexed)
__device__ __half2 d_Blo[(size_t)VPAD * NPAIR];
__device__ float   d_part[BDIM][NSC][160];
__device__ int     d_flag[VDIM];
__device__ int     d_cid[VDIM];                   // token -> compact id (0 if unused)
__device__ int     d_used[VPAD];                  // compact id -> token
__device__ int     d_count;

// ---------------------------------------------------------------------------
// helpers
// ---------------------------------------------------------------------------
__device__ __forceinline__ float logsig(float x) {
    return fminf(x, 0.0f) - log1pf(expf(-fabsf(x)));
}
// compact col c' -> diags/bias row (p*6 + m)
__device__ __forceinline__ int colmap(int c) {
    if (c < 150) { int p = c / 3;  int m = c - 3 * p;          return p * 6 + m; }
    if (c < 350) { int q = c - 150; int p = q >> 2; int m = q & 3;  return (50 + p) * 6 + m; }
    int q = c - 350; int p = q / 5; int m = q - 5 * p;         return (100 + p) * 6 + m;
}
__device__ __forceinline__ void cpa16(uint32_t dst, const void* src) {
    asm volatile("cp.async.cg.shared.global [%0], [%1], 16;" :: "r"(dst), "l"(src) : "memory");
}
#define CPA_COMMIT() asm volatile("cp.async.commit_group;" ::: "memory")
#define CPA_WAIT1()  asm volatile("cp.async.wait_group 1;" ::: "memory")
#define CPA_WAIT0()  asm volatile("cp.async.wait_group 0;" ::: "memory")

__device__ __forceinline__ uint32_t smem_u32(const void* p) {
    uint32_t a;
    asm("{ .reg .u64 t; cvta.to.shared.u64 t, %1; cvt.u32.u64 %0, t; }" : "=r"(a) : "l"(p));
    return a;
}

// pair-interleave within groups of 8 pairs: stored order (0,4,1,5,2,6,3,7)
__device__ __forceinline__ int pslot(int j) {
    return (j & ~7) + 2 * (j & 3) + ((j >> 2) & 1);
}

__device__ __forceinline__ void mma16816(float* d, uint32_t a0, uint32_t a1,
                                         uint32_t a2, uint32_t a3,
                                         uint32_t b0, uint32_t b1) {
    asm volatile(
        "mma.sync.aligned.m16n8k16.row.col.f32.f16.f16.f32 "
        "{%0,%1,%2,%3}, {%4,%5,%6,%7}, {%8,%9}, {%0,%1,%2,%3};"
        : "+f"(d[0]), "+f"(d[1]), "+f"(d[2]), "+f"(d[3])
        : "r"(a0), "r"(a1), "r"(a2), "r"(a3), "r"(b0), "r"(b1));
}

__device__ __forceinline__ void fp16split(float x, __half& h, __half& l) {
    h = __float2half_rn(x);
    l = __float2half_rn(x - __half2float(h));
}

// ---------------------------------------------------------------------------
// 0a. clear flags / maps / count
// ---------------------------------------------------------------------------
__global__ void clear_kernel() {
    int i = blockIdx.x * blockDim.x + threadIdx.x;
    if (i < VDIM) { d_flag[i] = 0; d_cid[i] = 0; }
    if (i < VPAD) d_used[i] = 0;
    if (i == 0) d_count = 0;
}

// 0b. mark tokens appearing within doc_lens
__global__ void mark_kernel(const int* __restrict__ docs,
                            const int* __restrict__ doc_lens) {
    int i = blockIdx.x * blockDim.x + threadIdx.x;     // over B*L
    int b = i >> 9, t = i & (LDIM - 1);
    if (b < BDIM && t < doc_lens[b]) d_flag[docs[i]] = 1;
}

// 0c. assign compact ids (warp-aggregated atomics)
__global__ void assign_kernel() {
    int v = blockIdx.x * blockDim.x + threadIdx.x;
    if (v >= VDIM) return;
    int lane = threadIdx.x & 31;
    int f = d_flag[v];
    unsigned mask = __ballot_sync(0xffffffffu, f != 0);
    int base = 0;
    if (lane == 0 && mask) base = atomicAdd(&d_count, __popc(mask));
    base = __shfl_sync(0xffffffffu, base, 0);
    if (f) {
        int cid = base + __popc(mask & ((1u << lane) - 1));
        d_cid[v] = cid;
        d_used[cid] = v;
    }
}

// ---------------------------------------------------------------------------
// 1. split diags -> fp16 hi/lo half2 pairs, [CPAD][NPAIR], pair-interleaved
// ---------------------------------------------------------------------------
__global__ void split_diags_kernel(const float* __restrict__ diags) {
    int i = blockIdx.x * blockDim.x + threadIdx.x;
    if (i >= CPAD * NPAIR) return;
    int c = i / NPAIR;
    int j = i - c * NPAIR;
    int k0 = 2 * j, k1 = 2 * j + 1;
    float x0 = 0.0f, x1 = 0.0f;
    if (c < CDIM) {
        int row = colmap(c);
        if (k0 < KDIM) x0 = diags[row * KDIM + k0];
        if (k1 < KDIM) x1 = diags[row * KDIM + k1];
    }
    __half h0, l0, h1, l1;
    fp16split(x0, h0, l0);
    fp16split(x1, h1, l1);
    int dst = c * NPAIR + pslot(j);
    d_Ahi[dst] = __halves2half2(h0, h1);
    d_Alo[dst] = __halves2half2(l0, l1);
}

// ---------------------------------------------------------------------------
// 2. transpose+split E -> B_hi/B_lo [VPAD][NPAIR], only USED token rows
// ---------------------------------------------------------------------------
__global__ void split_emb_kernel(const float* __restrict__ E) {
    __shared__ float tile[32][33];
    int vt = blockIdx.x * 32;
    int kt = blockIdx.y * 32;
    int tx = threadIdx.x, ty = threadIdx.y;   // (32, 8)
#pragma unroll
    for (int r = 0; r < 4; r++) {
        int k = kt + ty + r * 8, v = vt + tx;
        tile[ty + r * 8][tx] = (k < KDIM && v < VDIM) ? E[(size_t)k * VDIM + v] : 0.0f;
    }
    __syncthreads();
    int tid = ty * 32 + tx;
#pragma unroll
    for (int w = 0; w < 2; w++) {
        int idx = tid + 256 * w;               // 0..511 = 32 v x 16 pairs
        int j = idx & 15, vv = idx >> 4;
        int gp = (kt >> 1) + j;                // global pair index
        if (gp >= NPAIR) continue;
        int v = vt + vv;
        if (v >= VDIM || !d_flag[v]) continue; // skip unused tokens
        float x0 = tile[2 * j][vv];
        float x1 = tile[2 * j + 1][vv];
        __half h0, l0, h1, l1;
        fp16split(x0, h0, l0);
        fp16split(x1, h1, l1);
        size_t o = (size_t)v * NPAIR + pslot(gp);
        d_Bhi[o] = __halves2half2(h0, h1);
        d_Blo[o] = __halves2half2(l0, l1);
    }
}

// ---------------------------------------------------------------------------
// 3. GEMM over USED tokens only: D[128 cid x 128 c'] per CTA.
//    mma.sync m16n8k16 f16, 3x split; 19 k16 chunks, double-buffered.
// ---------------------------------------------------------------------------
#define ARR_BYTES   (128 * ASTR * 4)           // 6144
#define STAGE_BYTES (4 * ARR_BYTES)            // 24576
#define TOK_BYTES   512
#define GSMEM_TOTAL (2 * STAGE_BYTES + TOK_BYTES)  // 49664
#define OFF_AH 0
#define OFF_AL ARR_BYTES
#define OFF_BH (2 * ARR_BYTES)
#define OFF_BL (3 * ARR_BYTES)

__global__ void __launch_bounds__(256, 2)
gemm_mma_kernel(const float* __restrict__ bias) {
    extern __shared__ __align__(16) char smem[];
    const uint32_t sb = smem_u32(smem);
    int* s_tok = (int*)(smem + 2 * STAGE_BYTES);

    const int cnt = d_count;
    const int vBase = blockIdx.x * 128;        // compact-id base
    if (vBase >= cnt) return;

    const int tid = threadIdx.x;
    const int wid = tid >> 5;
    const int lid = tid & 31;
    const int g   = lid >> 2;
    const int t   = lid & 3;
    const int wm  = (wid & 3) * 32;
    const int wn  = (wid >> 2) * 64;
    const int cBase = blockIdx.y * 128;

    if (tid < 128) {
        int cid = vBase + tid;
        s_tok[tid] = d_used[(cid < cnt) ? cid : 0];
    }
    __syncthreads();

    const __half2* gAh = d_Ahi + (size_t)cBase * NPAIR;   // MMA B operand (n = c')
    const __half2* gAl = d_Alo + (size_t)cBase * NPAIR;

    auto load_chunk = [&](int kc, int s) {
        const uint32_t st = sb + s * STAGE_BYTES;
        const int p0 = kc * 8;                  // first pair of chunk
        int r = tid >> 1, q = (tid & 1) * 4;
        uint32_t so = (uint32_t)(r * ASTR + q) * 4;
        size_t gm = (size_t)s_tok[r] * NPAIR + p0 + q;    // gathered cid rows
        cpa16(st + OFF_AH + so, d_Bhi + gm);
        cpa16(st + OFF_AL + so, d_Blo + gm);
        size_t gn = (size_t)r * NPAIR + p0 + q;           // dense c' rows
        cpa16(st + OFF_BH + so, gAh + gn);
        cpa16(st + OFF_BL + so, gAl + gn);
        CPA_COMMIT();
    };

    float acc[2][8][4];
#pragma unroll
    for (int mi = 0; mi < 2; mi++)
#pragma unroll
        for (int ni = 0; ni < 8; ni++)
#pragma unroll
            for (int e = 0; e < 4; e++) acc[mi][ni][e] = 0.0f;

    load_chunk(0, 0);
    load_chunk(1, 1);

    for (int i = 0; i < NCHUNK; i++) {
        const int s = i & 1;
        if (i + 1 < NCHUNK) { CPA_WAIT1(); } else { CPA_WAIT0(); }
        __syncthreads();

        const float* sAh = (const float*)(smem + s * STAGE_BYTES + OFF_AH);
        const float* sAl = (const float*)(smem + s * STAGE_BYTES + OFF_AL);
        const float* sBh = (const float*)(smem + s * STAGE_BYTES + OFF_BH);
        const float* sBl = (const float*)(smem + s * STAGE_BYTES + OFF_BL);

        const int kcol = 2 * t;                 // pair-slot offset (floats)

        uint32_t Ah[2][4], Al[2][4];
#pragma unroll
        for (int mi = 0; mi < 2; mi++) {
            int r0 = wm + mi * 16 + g;
            float2 h0 = *(const float2*)&sAh[r0 * ASTR + kcol];
            float2 h1 = *(const float2*)&sAh[(r0 + 8) * ASTR + kcol];
            float2 l0 = *(const float2*)&sAl[r0 * ASTR + kcol];
            float2 l1 = *(const float2*)&sAl[(r0 + 8) * ASTR + kcol];
            Ah[mi][0] = __float_as_uint(h0.x); Ah[mi][1] = __float_as_uint(h1.x);
            Ah[mi][2] = __float_as_uint(h0.y); Ah[mi][3] = __float_as_uint(h1.y);
            Al[mi][0] = __float_as_uint(l0.x); Al[mi][1] = __float_as_uint(l1.x);
            Al[mi][2] = __float_as_uint(l0.y); Al[mi][3] = __float_as_uint(l1.y);
        }
#pragma unroll
        for (int ni = 0; ni < 8; ni++) {
            int rn = wn + ni * 8 + g;
            float2 h = *(const float2*)&sBh[rn * ASTR + kcol];
            float2 l = *(const float2*)&sBl[rn * ASTR + kcol];
            uint32_t bh0 = __float_as_uint(h.x), bh1 = __float_as_uint(h.y);
            uint32_t bl0 = __float_as_uint(l.x), bl1 = __float_as_uint(l.y);
#pragma unroll
            for (int mi = 0; mi < 2; mi++) {
                mma16816(acc[mi][ni], Ah[mi][0], Ah[mi][1], Ah[mi][2], Ah[mi][3], bh0, bh1);
                mma16816(acc[mi][ni], Ah[mi][0], Ah[mi][1], Ah[mi][2], Ah[mi][3], bl0, bl1);
                mma16816(acc[mi][ni], Al[mi][0], Al[mi][1], Al[mi][2], Al[mi][3], bh0, bh1);
            }
        }
        __syncthreads();
        if (i + 2 < NCHUNK) load_chunk(i + 2, s);
    }

    // ---- epilogue: +bias, logsig, float2 stores to table[cid][c'] ----
#pragma unroll
    for (int ni = 0; ni < 8; ni++) {
        const int c = cBase + wn + ni * 8 + 2 * t;
        if (c >= CDIM) continue;
        const int c1 = c + 1;
        const float b0 = __ldg(&bias[colmap(c)]);
        const float b1 = (c1 < CDIM) ? __ldg(&bias[colmap(c1)]) : 0.0f;
#pragma unroll
        for (int mi = 0; mi < 2; mi++) {
            const int v0 = vBase + wm + mi * 16 + g;
            const int v1 = v0 + 8;
            if (v0 < cnt) {
                float2 r;
                r.x = logsig(acc[mi][ni][0] + b0);
                r.y = logsig(acc[mi][ni][1] + b1);
                *(float2*)&d_table[(size_t)v0 * TSTR + c] = r;
            }
            if (v1 < cnt) {
                float2 r;
                r.x = logsig(acc[mi][ni][2] + b0);
                r.y = logsig(acc[mi][ni][3] + b1);
                *(float2*)&d_table[(size_t)v1 * TSTR + c] = r;
            }
        }
    }
}

// ---------------------------------------------------------------------------
// 4. chunked scan: block (b, ch) covers positions [ch*32, ch*32+32) with a
//    4-token warmup; tokens remapped to compact ids; per-p column offset.
//    Loads past a pattern's width read the neighbor's columns — harmless,
//    they only feed hidden states that are never selected for this p.
// ---------------------------------------------------------------------------
__global__ void __launch_bounds__(160)
scan_part_kernel(const int*   __restrict__ docs,
                 const int*   __restrict__ doc_lens,
                 const float* __restrict__ wildcards) {
    const int b   = blockIdx.x;
    const int ch  = blockIdx.y;
    const int tid = threadIdx.x;
    const int p   = tid;
    const bool valid = (p < PDIM);

    const int len = doc_lens[b];
    const int c0  = ch * SCT;
    if (len <= c0) {
        if (valid) d_part[b][ch][p] = NEGF;
        return;
    }

    const int warm   = (ch == 0) ? 0 : 4;
    const int tstart = c0 - warm;
    const int nt     = warm + SCT;   // 32 or 36

    __shared__ int s_tok[SCT + 4];
    for (int i = tid; i < nt; i += 160)
        s_tok[i] = d_cid[docs[b * LDIM + tstart + i]];
    __syncthreads();

    const int endSel = p / 50;                 // 0/1/2 -> width 3/4/5
    const int off    = (endSel == 0) ? 3 * p
                     : (endSel == 1) ? 4 * p - 50
                                     : 5 * p - 150;

    float wl[5];
#pragma unroll
    for (int m = 0; m < 5; m++)
        wl[m] = valid ? logsig(__ldg(&wildcards[p * 5 + m])) : 0.0f;

    float h1 = NEGF, h2 = NEGF, h3 = NEGF, h4 = NEGF, h5 = NEGF;
    float sc = NEGF;

    float pf[4][5];
#pragma unroll
    for (int u = 0; u < 4; u++) {
        if (valid && u < nt) {
            const float* row = &d_table[(size_t)s_tok[u] * TSTR + off];
#pragma unroll
            for (int m = 0; m < 5; m++) pf[u][m] = __ldg(&row[m]);
        } else {
#pragma unroll
            for (int m = 0; m < 5; m++) pf[u][m] = 0.0f;
        }
    }

    const int scoreLo = warm;
    const int scoreHi = (len < c0 + SCT ? len : c0 + SCT) - tstart;

    for (int i = 0; i < nt; i += 4) {
#pragma unroll
        for (int u = 0; u < 4; u++) {
            float e0 = fmaxf(pf[u][0], wl[0]);
            float e1 = fmaxf(pf[u][1], wl[1]);
            float e2 = fmaxf(pf[u][2], wl[2]);
            float e3 = fmaxf(pf[u][3], wl[3]);
            float e4 = fmaxf(pf[u][4], wl[4]);
            h5 = h4 + e4;
            h4 = h3 + e3;
            h3 = h2 + e2;
            h2 = h1 + e1;
            h1 = e0;
            float ev = (endSel == 0) ? h3 : ((endSel == 1) ? h4 : h5);
            int li = i + u;
            sc = (li >= scoreLo && li < scoreHi) ? fmaxf(sc, ev) : sc;
            int ni = li + 4;
            if (ni < nt && valid) {
                const float* row = &d_table[(size_t)s_tok[ni] * TSTR + off];
#pragma unroll
                for (int m = 0; m < 5; m++) pf[u][m] = __ldg(&row[m]);
            }
        }
    }

    if (valid) d_part[b][ch][p] = sc;
}

// ---------------------------------------------------------------------------
// 5. final: reduce chunks, exp/LN/heaviside/linear
// ---------------------------------------------------------------------------
__global__ void __launch_bounds__(160)
scan_final_kernel(const float* __restrict__ gamma,
                  const float* __restrict__ beta,
                  const float* __restrict__ W,
                  const float* __restrict__ lb,
                  float*       __restrict__ out) {
    const int b   = blockIdx.x;
    const int tid = threadIdx.x;
    const bool valid = (tid < PDIM);

    __shared__ float sh[192];
    __shared__ float sred[2];

    float sc = NEGF;
    if (valid) {
#pragma unroll
        for (int ch = 0; ch < NSC; ch++) sc = fmaxf(sc, d_part[b][ch][tid]);
    }
    float score = valid ? expf(sc) : 0.0f;

    sh[tid] = score;
    __syncthreads();
    if (tid < 32) {
        float s = 0.0f;
        for (int i = tid; i < PDIM; i += 32) s += sh[i];
#pragma unroll
        for (int o = 16; o > 0; o >>= 1) s += __shfl_down_sync(0xffffffffu, s, o);
        if (tid == 0) sred[0] = s * (1.0f / PDIM);
    }
    __syncthreads();
    const float mu = sred[0];

    float d = score - mu;
    sh[tid] = valid ? d * d : 0.0f;
    __syncthreads();
    if (tid < 32) {
        float s = 0.0f;
        for (int i = tid; i < PDIM; i += 32) s += sh[i];
#pragma unroll
        for (int o = 16; o > 0; o >>= 1) s += __shfl_down_sync(0xffffffffu, s, o);
        if (tid == 0) sred[1] = s * (1.0f / PDIM);
    }
    __syncthreads();
    const float var = sred[1];

    float bin = 0.0f;
    if (valid) {
        float norm = (score - mu) * rsqrtf(var + 1e-5f) * __ldg(&gamma[tid]) + __ldg(&beta[tid]);
        bin = (norm > 0.0f) ? 1.0f : 0.0f;
    }

    sh[tid] = valid ? bin * __ldg(&W[tid]) : 0.0f;
    __syncthreads();
    if (tid < 32) {
        float s = 0.0f;
        for (int i = tid; i < PDIM; i += 32) s += sh[i];
#pragma unroll
        for (int o = 16; o > 0; o >>= 1) s += __shfl_down_sync(0xffffffffu, s, o);
        if (tid == 0) out[b * 2 + 0] = s + __ldg(&lb[0]);
    }
    __syncthreads();
    sh[tid] = valid ? bin * __ldg(&W[PDIM + tid]) : 0.0f;
    __syncthreads();
    if (tid < 32) {
        float s = 0.0f;
        for (int i = tid; i < PDIM; i += 32) s += sh[i];
#pragma unroll
        for (int o = 16; o > 0; o >>= 1) s += __shfl_down_sync(0xffffffffu, s, o);
        if (tid == 0) out[b * 2 + 1] = s + __ldg(&lb[1]);
    }
}

// ---------------------------------------------------------------------------
// launch
// ---------------------------------------------------------------------------
extern "C" void kernel_launch(void* const* d_in, const int* in_sizes, int n_in,
                              void* d_out, int out_size) {
    const int*   docs      = (const int*)  d_in[0];
    const int*   doc_lens  = (const int*)  d_in[1];
    const float* emb       = (const float*)d_in[2];
    const float* diags     = (const float*)d_in[3];
    const float* bias      = (const float*)d_in[4];
    const float* wildcards = (const float*)d_in[5];
    const float* ln_gamma  = (const float*)d_in[6];
    const float* ln_beta   = (const float*)d_in[7];
    const float* linear_w  = (const float*)d_in[8];
    const float* linear_b  = (const float*)d_in[9];
    float*       out       = (float*)d_out;

    (void)in_sizes; (void)n_in; (void)out_size;

    cudaFuncSetAttribute(gemm_mma_kernel,
                         cudaFuncAttributeMaxDynamicSharedMemorySize, GSMEM_TOTAL);

    clear_kernel<<<(VPAD + 255) / 256, 256>>>();
    mark_kernel<<<(BDIM * LDIM + 255) / 256, 256>>>(docs, doc_lens);
    assign_kernel<<<(VDIM + 255) / 256, 256>>>();

    split_diags_kernel<<<(CPAD * NPAIR + 255) / 256, 256>>>(diags);

    dim3 tgrid((VPAD + 31) / 32, (KPAD + 31) / 32);  // (628, 10)
    split_emb_kernel<<<tgrid, dim3(32, 8)>>>(emb);

    dim3 ggrid(VPAD / 128, CPAD / 128);              // (157, 5)
    gemm_mma_kernel<<<ggrid, 256, GSMEM_TOTAL>>>(bias);

    dim3 sgrid(BDIM, NSC);                           // (64, 16)
    scan_part_kernel<<<sgrid, 160>>>(docs, doc_lens, wildcards);

    scan_final_kernel<<<BDIM, 160>>>(ln_gamma, ln_beta, linear_w, linear_b, out);
}

// round 12
// speedup vs baseline: 1.1964x; 1.0010x over previous
#include <cuda_runtime.h>
#include <cuda_fp16.h>
#include <cstdint>

// ---------------------------------------------------------------------------
// SoftPatternClassifier on GB300 — vocab+column-compacted 3xFP16 GEMM
//   R12: scan interleaves 2 time-chunks per thread (2x MLP);
//        prep fused: (clear+split_diags), (assign+split_emb).
// ---------------------------------------------------------------------------

#define BDIM 64
#define LDIM 512
#define VDIM 20000
#define PDIM 150
#define CDIM 600              // compacted transition columns
#define KDIM 300
#define NEGF (-1000000000.0f)

#define TSTR 640              // table row stride (= CPAD)
#define KPAD 304              // 19 chunks of 16
#define NPAIR (KPAD / 2)      // 152 half2 pairs per row
#define CPAD 640              // 5 * 128
#define VPAD 20096            // 157 * 128

#define TK 16
#define NCHUNK (KPAD / TK)    // 19
#define ASTR 12               // smem row stride (floats); payload 8

#define NSC 16                // scan time-chunks
#define SCT 32                // positions per scan chunk

// __device__ scratch (allocation-free rule)
__device__ float   d_table[(size_t)VPAD * TSTR];  // ~51 MB (cid-indexed)
__device__ __half2 d_Ahi[CPAD * NPAIR];
__device__ __half2 d_Alo[CPAD * NPAIR];
__device__ __half2 d_Bhi[(size_t)VPAD * NPAIR];   // ~6.1 MB (token-indexed)
__device__ __half2 d_Blo[(size_t)VPAD * NPAIR];
__device__ float   d_part[BDIM][NSC][160];
__device__ int     d_flag[VDIM];
__device__ int     d_cid[VDIM];
__device__ int     d_used[VPAD];
__device__ int     d_count;

// ---------------------------------------------------------------------------
// helpers
// ---------------------------------------------------------------------------
__device__ __forceinline__ float logsig(float x) {
    return fminf(x, 0.0f) - log1pf(expf(-fabsf(x)));
}
// compact col c' -> diags/bias row (p*6 + m)
__device__ __forceinline__ int colmap(int c) {
    if (c < 150) { int p = c / 3;  int m = c - 3 * p;          return p * 6 + m; }
    if (c < 350) { int q = c - 150; int p = q >> 2; int m = q & 3;  return (50 + p) * 6 + m; }
    int q = c - 350; int p = q / 5; int m = q - 5 * p;         return (100 + p) * 6 + m;
}
__device__ __forceinline__ void cpa16(uint32_t dst, const void* src) {
    asm volatile("cp.async.cg.shared.global [%0], [%1], 16;" :: "r"(dst), "l"(src) : "memory");
}
#define CPA_COMMIT() asm volatile("cp.async.commit_group;" ::: "memory")
#define CPA_WAIT1()  asm volatile("cp.async.wait_group 1;" ::: "memory")
#define CPA_WAIT0()  asm volatile("cp.async.wait_group 0;" ::: "memory")

__device__ __forceinline__ uint32_t smem_u32(const void* p) {
    uint32_t a;
    asm("{ .reg .u64 t; cvta.to.shared.u64 t, %1; cvt.u32.u64 %0, t; }" : "=r"(a) : "l"(p));
    return a;
}

// pair-interleave within groups of 8 pairs: stored order (0,4,1,5,2,6,3,7)
__device__ __forceinline__ int pslot(int j) {
    return (j & ~7) + 2 * (j & 3) + ((j >> 2) & 1);
}

__device__ __forceinline__ void mma16816(float* d, uint32_t a0, uint32_t a1,
                                         uint32_t a2, uint32_t a3,
                                         uint32_t b0, uint32_t b1) {
    asm volatile(
        "mma.sync.aligned.m16n8k16.row.col.f32.f16.f16.f32 "
        "{%0,%1,%2,%3}, {%4,%5,%6,%7}, {%8,%9}, {%0,%1,%2,%3};"
        : "+f"(d[0]), "+f"(d[1]), "+f"(d[2]), "+f"(d[3])
        : "r"(a0), "r"(a1), "r"(a2), "r"(a3), "r"(b0), "r"(b1));
}

__device__ __forceinline__ void fp16split(float x, __half& h, __half& l) {
    h = __float2half_rn(x);
    l = __float2half_rn(x - __half2float(h));
}

// ---------------------------------------------------------------------------
// A. fused: split_diags (blocks [0,380)) + clear (blocks [380,459))
// ---------------------------------------------------------------------------
#define SD_BLOCKS ((CPAD * NPAIR + 255) / 256)         // 380
#define CL_BLOCKS ((VPAD + 255) / 256)                 // 79

__global__ void prepA_kernel(const float* __restrict__ diags) {
    if (blockIdx.x >= SD_BLOCKS) {
        int i = (blockIdx.x - SD_BLOCKS) * blockDim.x + threadIdx.x;
        if (i < VDIM) { d_flag[i] = 0; d_cid[i] = 0; }
        if (i < VPAD) d_used[i] = 0;
        if (i == 0) d_count = 0;
        return;
    }
    int i = blockIdx.x * blockDim.x + threadIdx.x;
    if (i >= CPAD * NPAIR) return;
    int c = i / NPAIR;
    int j = i - c * NPAIR;
    int k0 = 2 * j, k1 = 2 * j + 1;
    float x0 = 0.0f, x1 = 0.0f;
    if (c < CDIM) {
        int row = colmap(c);
        if (k0 < KDIM) x0 = diags[row * KDIM + k0];
        if (k1 < KDIM) x1 = diags[row * KDIM + k1];
    }
    __half h0, l0, h1, l1;
    fp16split(x0, h0, l0);
    fp16split(x1, h1, l1);
    int dst = c * NPAIR + pslot(j);
    d_Ahi[dst] = __halves2half2(h0, h1);
    d_Alo[dst] = __halves2half2(l0, l1);
}

// ---------------------------------------------------------------------------
// B. mark tokens appearing within doc_lens
// ---------------------------------------------------------------------------
__global__ void mark_kernel(const int* __restrict__ docs,
                            const int* __restrict__ doc_lens) {
    int i = blockIdx.x * blockDim.x + threadIdx.x;
    int b = i >> 9, t = i & (LDIM - 1);
    if (b < BDIM && t < doc_lens[b]) d_flag[docs[i]] = 1;
}

// ---------------------------------------------------------------------------
// C. fused: split_emb (y in [0,10)) + assign (y == 10, x < 79)
// ---------------------------------------------------------------------------
__global__ void prepC_kernel(const float* __restrict__ E) {
    int tx = threadIdx.x, ty = threadIdx.y;   // (32, 8)
    int tid = ty * 32 + tx;

    if (blockIdx.y == (KPAD + 31) / 32) {     // assign row
        if (blockIdx.x >= CL_BLOCKS) return;
        int v = blockIdx.x * 256 + tid;
        if (v >= VDIM) return;
        int lane = tx;
        int f = d_flag[v];
        unsigned mask = __ballot_sync(0xffffffffu, f != 0);
        int base = 0;
        if (lane == 0 && mask) base = atomicAdd(&d_count, __popc(mask));
        base = __shfl_sync(0xffffffffu, base, 0);
        if (f) {
            int cid = base + __popc(mask & ((1u << lane) - 1));
            d_cid[v] = cid;
            d_used[cid] = v;
        }
        return;
    }

    __shared__ float tile[32][33];
    int vt = blockIdx.x * 32;
    int kt = blockIdx.y * 32;
#pragma unroll
    for (int r = 0; r < 4; r++) {
        int k = kt + ty + r * 8, v = vt + tx;
        tile[ty + r * 8][tx] = (k < KDIM && v < VDIM) ? E[(size_t)k * VDIM + v] : 0.0f;
    }
    __syncthreads();
#pragma unroll
    for (int w = 0; w < 2; w++) {
        int idx = tid + 256 * w;               // 0..511 = 32 v x 16 pairs
        int j = idx & 15, vv = idx >> 4;
        int gp = (kt >> 1) + j;
        if (gp >= NPAIR) continue;
        int v = vt + vv;
        if (v >= VDIM || !d_flag[v]) continue;
        float x0 = tile[2 * j][vv];
        float x1 = tile[2 * j + 1][vv];
        __half h0, l0, h1, l1;
        fp16split(x0, h0, l0);
        fp16split(x1, h1, l1);
        size_t o = (size_t)v * NPAIR + pslot(gp);
        d_Bhi[o] = __halves2half2(h0, h1);
        d_Blo[o] = __halves2half2(l0, l1);
    }
}

// ---------------------------------------------------------------------------
// D. GEMM over USED tokens only: D[128 cid x 128 c'] per CTA.
// ---------------------------------------------------------------------------
#define ARR_BYTES   (128 * ASTR * 4)           // 6144
#define STAGE_BYTES (4 * ARR_BYTES)            // 24576
#define TOK_BYTES   512
#define GSMEM_TOTAL (2 * STAGE_BYTES + TOK_BYTES)  // 49664
#define OFF_AH 0
#define OFF_AL ARR_BYTES
#define OFF_BH (2 * ARR_BYTES)
#define OFF_BL (3 * ARR_BYTES)

__global__ void __launch_bounds__(256, 2)
gemm_mma_kernel(const float* __restrict__ bias) {
    extern __shared__ __align__(16) char smem[];
    const uint32_t sb = smem_u32(smem);
    int* s_tok = (int*)(smem + 2 * STAGE_BYTES);

    const int cnt = d_count;
    const int vBase = blockIdx.x * 128;
    if (vBase >= cnt) return;

    const int tid = threadIdx.x;
    const int wid = tid >> 5;
    const int lid = tid & 31;
    const int g   = lid >> 2;
    const int t   = lid & 3;
    const int wm  = (wid & 3) * 32;
    const int wn  = (wid >> 2) * 64;
    const int cBase = blockIdx.y * 128;

    if (tid < 128) {
        int cid = vBase + tid;
        s_tok[tid] = d_used[(cid < cnt) ? cid : 0];
    }
    __syncthreads();

    const __half2* gAh = d_Ahi + (size_t)cBase * NPAIR;
    const __half2* gAl = d_Alo + (size_t)cBase * NPAIR;

    auto load_chunk = [&](int kc, int s) {
        const uint32_t st = sb + s * STAGE_BYTES;
        const int p0 = kc * 8;
        int r = tid >> 1, q = (tid & 1) * 4;
        uint32_t so = (uint32_t)(r * ASTR + q) * 4;
        size_t gm = (size_t)s_tok[r] * NPAIR + p0 + q;
        cpa16(st + OFF_AH + so, d_Bhi + gm);
        cpa16(st + OFF_AL + so, d_Blo + gm);
        size_t gn = (size_t)r * NPAIR + p0 + q;
        cpa16(st + OFF_BH + so, gAh + gn);
        cpa16(st + OFF_BL + so, gAl + gn);
        CPA_COMMIT();
    };

    float acc[2][8][4];
#pragma unroll
    for (int mi = 0; mi < 2; mi++)
#pragma unroll
        for (int ni = 0; ni < 8; ni++)
#pragma unroll
            for (int e = 0; e < 4; e++) acc[mi][ni][e] = 0.0f;

    load_chunk(0, 0);
    load_chunk(1, 1);

    for (int i = 0; i < NCHUNK; i++) {
        const int s = i & 1;
        if (i + 1 < NCHUNK) { CPA_WAIT1(); } else { CPA_WAIT0(); }
        __syncthreads();

        const float* sAh = (const float*)(smem + s * STAGE_BYTES + OFF_AH);
        const float* sAl = (const float*)(smem + s * STAGE_BYTES + OFF_AL);
        const float* sBh = (const float*)(smem + s * STAGE_BYTES + OFF_BH);
        const float* sBl = (const float*)(smem + s * STAGE_BYTES + OFF_BL);

        const int kcol = 2 * t;

        uint32_t Ah[2][4], Al[2][4];
#pragma unroll
        for (int mi = 0; mi < 2; mi++) {
            int r0 = wm + mi * 16 + g;
            float2 h0 = *(const float2*)&sAh[r0 * ASTR + kcol];
            float2 h1 = *(const float2*)&sAh[(r0 + 8) * ASTR + kcol];
            float2 l0 = *(const float2*)&sAl[r0 * ASTR + kcol];
            float2 l1 = *(const float2*)&sAl[(r0 + 8) * ASTR + kcol];
            Ah[mi][0] = __float_as_uint(h0.x); Ah[mi][1] = __float_as_uint(h1.x);
            Ah[mi][2] = __float_as_uint(h0.y); Ah[mi][3] = __float_as_uint(h1.y);
            Al[mi][0] = __float_as_uint(l0.x); Al[mi][1] = __float_as_uint(l1.x);
            Al[mi][2] = __float_as_uint(l0.y); Al[mi][3] = __float_as_uint(l1.y);
        }
#pragma unroll
        for (int ni = 0; ni < 8; ni++) {
            int rn = wn + ni * 8 + g;
            float2 h = *(const float2*)&sBh[rn * ASTR + kcol];
            float2 l = *(const float2*)&sBl[rn * ASTR + kcol];
            uint32_t bh0 = __float_as_uint(h.x), bh1 = __float_as_uint(h.y);
            uint32_t bl0 = __float_as_uint(l.x), bl1 = __float_as_uint(l.y);
#pragma unroll
            for (int mi = 0; mi < 2; mi++) {
                mma16816(acc[mi][ni], Ah[mi][0], Ah[mi][1], Ah[mi][2], Ah[mi][3], bh0, bh1);
                mma16816(acc[mi][ni], Ah[mi][0], Ah[mi][1], Ah[mi][2], Ah[mi][3], bl0, bl1);
                mma16816(acc[mi][ni], Al[mi][0], Al[mi][1], Al[mi][2], Al[mi][3], bh0, bh1);
            }
        }
        __syncthreads();
        if (i + 2 < NCHUNK) load_chunk(i + 2, s);
    }

    // ---- epilogue ----
#pragma unroll
    for (int ni = 0; ni < 8; ni++) {
        const int c = cBase + wn + ni * 8 + 2 * t;
        if (c >= CDIM) continue;
        const int c1 = c + 1;
        const float b0 = __ldg(&bias[colmap(c)]);
        const float b1 = (c1 < CDIM) ? __ldg(&bias[colmap(c1)]) : 0.0f;
#pragma unroll
        for (int mi = 0; mi < 2; mi++) {
            const int v0 = vBase + wm + mi * 16 + g;
            const int v1 = v0 + 8;
            if (v0 < cnt) {
                float2 r;
                r.x = logsig(acc[mi][ni][0] + b0);
                r.y = logsig(acc[mi][ni][1] + b1);
                *(float2*)&d_table[(size_t)v0 * TSTR + c] = r;
            }
            if (v1 < cnt) {
                float2 r;
                r.x = logsig(acc[mi][ni][2] + b0);
                r.y = logsig(acc[mi][ni][3] + b1);
                *(float2*)&d_table[(size_t)v1 * TSTR + c] = r;
            }
        }
    }
}

// ---------------------------------------------------------------------------
// E. scan: block (b, q) handles chunks ch=2q and 2q+1, interleaved per
//    thread (2 independent chains -> 2x outstanding loads). Uniform 36-step
//    loop; ch=0 clamps tstart to 0 and scores [0,32).
// ---------------------------------------------------------------------------
#define NTS 36

__global__ void __launch_bounds__(160)
scan_part_kernel(const int*   __restrict__ docs,
                 const int*   __restrict__ doc_lens,
                 const float* __restrict__ wildcards) {
    const int b   = blockIdx.x;
    const int q   = blockIdx.y;
    const int tid = threadIdx.x;
    const int p   = tid;
    const bool valid = (p < PDIM);

    const int ch0 = 2 * q, ch1 = 2 * q + 1;
    const int len = doc_lens[b];
    const int c00 = ch0 * SCT, c01 = ch1 * SCT;

    if (len <= c00) {
        if (valid) { d_part[b][ch0][p] = NEGF; d_part[b][ch1][p] = NEGF; }
        return;
    }

    const int ts0 = (c00 >= 4) ? c00 - 4 : 0;
    const int ts1 = c01 - 4;

    __shared__ int tok[2][NTS];
    for (int i = tid; i < 2 * NTS; i += 160) {
        int j = i / NTS, ii = i - j * NTS;
        int ts = j ? ts1 : ts0;
        int gi = ts + ii; if (gi >= LDIM) gi = LDIM - 1;
        tok[j][ii] = d_cid[docs[b * LDIM + gi]];
    }
    __syncthreads();

    const int endSel = p / 50;
    const int off    = (endSel == 0) ? 3 * p
                     : (endSel == 1) ? 4 * p - 50
                                     : 5 * p - 150;

    float wl[5];
#pragma unroll
    for (int m = 0; m < 5; m++)
        wl[m] = valid ? logsig(__ldg(&wildcards[p * 5 + m])) : 0.0f;

    float ha[2][5], sc[2];
    float pf[2][4][5];
#pragma unroll
    for (int j = 0; j < 2; j++) {
        sc[j] = NEGF;
#pragma unroll
        for (int m = 0; m < 5; m++) ha[j][m] = NEGF;
#pragma unroll
        for (int u = 0; u < 4; u++) {
            if (valid) {
                const float* row = &d_table[(size_t)tok[j][u] * TSTR + off];
#pragma unroll
                for (int m = 0; m < 5; m++) pf[j][u][m] = __ldg(&row[m]);
            } else {
#pragma unroll
                for (int m = 0; m < 5; m++) pf[j][u][m] = 0.0f;
            }
        }
    }

    const int lo0 = c00 - ts0;
    const int hi0 = (len < c00 + SCT ? len : c00 + SCT) - ts0;
    const int lo1 = 4;
    const int hi1 = (len < c01 + SCT ? len : c01 + SCT) - ts1;   // may be <= 4

    for (int i = 0; i < NTS; i += 4) {
#pragma unroll
        for (int u = 0; u < 4; u++) {
            const int li = i + u;
            const int ni = li + 4;
#pragma unroll
            for (int j = 0; j < 2; j++) {
                float e0 = fmaxf(pf[j][u][0], wl[0]);
                float e1 = fmaxf(pf[j][u][1], wl[1]);
                float e2 = fmaxf(pf[j][u][2], wl[2]);
                float e3 = fmaxf(pf[j][u][3], wl[3]);
                float e4 = fmaxf(pf[j][u][4], wl[4]);
                ha[j][4] = ha[j][3] + e4;
                ha[j][3] = ha[j][2] + e3;
                ha[j][2] = ha[j][1] + e2;
                ha[j][1] = ha[j][0] + e1;
                ha[j][0] = e0;
                float ev = (endSel == 0) ? ha[j][2]
                         : (endSel == 1) ? ha[j][3] : ha[j][4];
                const int lo = j ? lo1 : lo0;
                const int hi = j ? hi1 : hi0;
                sc[j] = (li >= lo && li < hi) ? fmaxf(sc[j], ev) : sc[j];
                if (ni < NTS && valid) {
                    const float* row = &d_table[(size_t)tok[j][ni] * TSTR + off];
#pragma unroll
                    for (int m = 0; m < 5; m++) pf[j][u][m] = __ldg(&row[m]);
                }
            }
        }
    }

    if (valid) {
        d_part[b][ch0][p] = sc[0];
        d_part[b][ch1][p] = sc[1];
    }
}

// ---------------------------------------------------------------------------
// F. final: reduce chunks, exp/LN/heaviside/linear
// ---------------------------------------------------------------------------
__global__ void __launch_bounds__(160)
scan_final_kernel(const float* __restrict__ gamma,
                  const float* __restrict__ beta,
                  const float* __restrict__ W,
                  const float* __restrict__ lb,
                  float*       __restrict__ out) {
    const int b   = blockIdx.x;
    const int tid = threadIdx.x;
    const bool valid = (tid < PDIM);

    __shared__ float sh[192];
    __shared__ float sred[2];

    float sc = NEGF;
    if (valid) {
#pragma unroll
        for (int ch = 0; ch < NSC; ch++) sc = fmaxf(sc, d_part[b][ch][tid]);
    }
    float score = valid ? expf(sc) : 0.0f;

    sh[tid] = score;
    __syncthreads();
    if (tid < 32) {
        float s = 0.0f;
        for (int i = tid; i < PDIM; i += 32) s += sh[i];
#pragma unroll
        for (int o = 16; o > 0; o >>= 1) s += __shfl_down_sync(0xffffffffu, s, o);
        if (tid == 0) sred[0] = s * (1.0f / PDIM);
    }
    __syncthreads();
    const float mu = sred[0];

    float d = score - mu;
    sh[tid] = valid ? d * d : 0.0f;
    __syncthreads();
    if (tid < 32) {
        float s = 0.0f;
        for (int i = tid; i < PDIM; i += 32) s += sh[i];
#pragma unroll
        for (int o = 16; o > 0; o >>= 1) s += __shfl_down_sync(0xffffffffu, s, o);
        if (tid == 0) sred[1] = s * (1.0f / PDIM);
    }
    __syncthreads();
    const float var = sred[1];

    float bin = 0.0f;
    if (valid) {
        float norm = (score - mu) * rsqrtf(var + 1e-5f) * __ldg(&gamma[tid]) + __ldg(&beta[tid]);
        bin = (norm > 0.0f) ? 1.0f : 0.0f;
    }

    sh[tid] = valid ? bin * __ldg(&W[tid]) : 0.0f;
    __syncthreads();
    if (tid < 32) {
        float s = 0.0f;
        for (int i = tid; i < PDIM; i += 32) s += sh[i];
#pragma unroll
        for (int o = 16; o > 0; o >>= 1) s += __shfl_down_sync(0xffffffffu, s, o);
        if (tid == 0) out[b * 2 + 0] = s + __ldg(&lb[0]);
    }
    __syncthreads();
    sh[tid] = valid ? bin * __ldg(&W[PDIM + tid]) : 0.0f;
    __syncthreads();
    if (tid < 32) {
        float s = 0.0f;
        for (int i = tid; i < PDIM; i += 32) s += sh[i];
#pragma unroll
        for (int o = 16; o > 0; o >>= 1) s += __shfl_down_sync(0xffffffffu, s, o);
        if (tid == 0) out[b * 2 + 1] = s + __ldg(&lb[1]);
    }
}

// ---------------------------------------------------------------------------
// launch
// ---------------------------------------------------------------------------
extern "C" void kernel_launch(void* const* d_in, const int* in_sizes, int n_in,
                              void* d_out, int out_size) {
    const int*   docs      = (const int*)  d_in[0];
    const int*   doc_lens  = (const int*)  d_in[1];
    const float* emb       = (const float*)d_in[2];
    const float* diags     = (const float*)d_in[3];
    const float* bias      = (const float*)d_in[4];
    const float* wildcards = (const float*)d_in[5];
    const float* ln_gamma  = (const float*)d_in[6];
    const float* ln_beta   = (const float*)d_in[7];
    const float* linear_w  = (const float*)d_in[8];
    const float* linear_b  = (const float*)d_in[9];
    float*       out       = (float*)d_out;

    (void)in_sizes; (void)n_in; (void)out_size;

    cudaFuncSetAttribute(gemm_mma_kernel,
                         cudaFuncAttributeMaxDynamicSharedMemorySize, GSMEM_TOTAL);

    prepA_kernel<<<SD_BLOCKS + CL_BLOCKS, 256>>>(diags);          // split_diags + clear
    mark_kernel<<<(BDIM * LDIM + 255) / 256, 256>>>(docs, doc_lens);

    dim3 cgrid((VPAD + 31) / 32, (KPAD + 31) / 32 + 1);           // (628, 11): emb + assign
    prepC_kernel<<<cgrid, dim3(32, 8)>>>(emb);

    dim3 ggrid(VPAD / 128, CPAD / 128);                           // (157, 5)
    gemm_mma_kernel<<<ggrid, 256, GSMEM_TOTAL>>>(bias);

    dim3 sgrid(BDIM, NSC / 2);                                    // (64, 8)
    scan_part_kernel<<<sgrid, 160>>>(docs, doc_lens, wildcards);

    scan_final_kernel<<<BDIM, 160>>>(ln_gamma, ln_beta, linear_w, linear_b, out);
}

// round 13
// speedup vs baseline: 1.2057x; 1.0078x over previous
#include <cuda_runtime.h>
#include <cuda_fp16.h>
#include <cstdint>

// ---------------------------------------------------------------------------
// SoftPatternClassifier on GB300 — vocab+column-compacted 3xFP16 GEMM
//   R13: hi/lo packed per pair (uint2) -> one LDS.128 feeds both split
//        operands: shared loads 24 -> 12 per chunk, address ALU halved.
// ---------------------------------------------------------------------------

#define BDIM 64
#define LDIM 512
#define VDIM 20000
#define PDIM 150
#define CDIM 600              // compacted transition columns
#define KDIM 300
#define NEGF (-1000000000.0f)

#define TSTR 640              // table row stride (= CPAD)
#define KPAD 304              // 19 chunks of 16
#define NPAIR (KPAD / 2)      // 152 half2 pairs per row
#define CPAD 640              // 5 * 128
#define VPAD 20096            // 157 * 128

#define TK 16
#define NCHUNK (KPAD / TK)    // 19

#define NSC 16                // scan time-chunks
#define SCT 32                // positions per scan chunk

// __device__ scratch (allocation-free rule)
__device__ float d_table[(size_t)VPAD * TSTR];   // ~51 MB (cid-indexed)
__device__ uint2 d_Ac[CPAD * NPAIR];             // (hi2, lo2) packed, c rows
__device__ uint2 d_Bc[(size_t)VPAD * NPAIR];     // (hi2, lo2) packed, token rows
__device__ float d_part[BDIM][NSC][160];
__device__ int   d_flag[VDIM];
__device__ int   d_cid[VDIM];
__device__ int   d_used[VPAD];
__device__ int   d_count;

// ---------------------------------------------------------------------------
// helpers
// ---------------------------------------------------------------------------
__device__ __forceinline__ float logsig(float x) {
    return fminf(x, 0.0f) - log1pf(expf(-fabsf(x)));
}
// compact col c' -> diags/bias row (p*6 + m)
__device__ __forceinline__ int colmap(int c) {
    if (c < 150) { int p = c / 3;  int m = c - 3 * p;          return p * 6 + m; }
    if (c < 350) { int q = c - 150; int p = q >> 2; int m = q & 3;  return (50 + p) * 6 + m; }
    int q = c - 350; int p = q / 5; int m = q - 5 * p;         return (100 + p) * 6 + m;
}
__device__ __forceinline__ void cpa16(uint32_t dst, const void* src) {
    asm volatile("cp.async.cg.shared.global [%0], [%1], 16;" :: "r"(dst), "l"(src) : "memory");
}
#define CPA_COMMIT() asm volatile("cp.async.commit_group;" ::: "memory")
#define CPA_WAIT1()  asm volatile("cp.async.wait_group 1;" ::: "memory")
#define CPA_WAIT0()  asm volatile("cp.async.wait_group 0;" ::: "memory")

__device__ __forceinline__ uint32_t smem_u32(const void* p) {
    uint32_t a;
    asm("{ .reg .u64 t; cvta.to.shared.u64 t, %1; cvt.u32.u64 %0, t; }" : "=r"(a) : "l"(p));
    return a;
}

// pair-interleave within groups of 8 pairs: stored order (0,4,1,5,2,6,3,7)
__device__ __forceinline__ int pslot(int j) {
    return (j & ~7) + 2 * (j & 3) + ((j >> 2) & 1);
}

__device__ __forceinline__ void mma16816(float* d, uint32_t a0, uint32_t a1,
                                         uint32_t a2, uint32_t a3,
                                         uint32_t b0, uint32_t b1) {
    asm volatile(
        "mma.sync.aligned.m16n8k16.row.col.f32.f16.f16.f32 "
        "{%0,%1,%2,%3}, {%4,%5,%6,%7}, {%8,%9}, {%0,%1,%2,%3};"
        : "+f"(d[0]), "+f"(d[1]), "+f"(d[2]), "+f"(d[3])
        : "r"(a0), "r"(a1), "r"(a2), "r"(a3), "r"(b0), "r"(b1));
}

__device__ __forceinline__ uint2 fp16pack(float x0, float x1) {
    __half h0 = __float2half_rn(x0);
    __half h1 = __float2half_rn(x1);
    __half l0 = __float2half_rn(x0 - __half2float(h0));
    __half l1 = __float2half_rn(x1 - __half2float(h1));
    __half2 hh = __halves2half2(h0, h1);
    __half2 ll = __halves2half2(l0, l1);
    uint2 r;
    r.x = *reinterpret_cast<uint32_t*>(&hh);
    r.y = *reinterpret_cast<uint32_t*>(&ll);
    return r;
}

// ---------------------------------------------------------------------------
// A. fused: split_diags (blocks [0,380)) + clear (blocks [380,459))
// ---------------------------------------------------------------------------
#define SD_BLOCKS ((CPAD * NPAIR + 255) / 256)         // 380
#define CL_BLOCKS ((VPAD + 255) / 256)                 // 79

__global__ void prepA_kernel(const float* __restrict__ diags) {
    if (blockIdx.x >= SD_BLOCKS) {
        int i = (blockIdx.x - SD_BLOCKS) * blockDim.x + threadIdx.x;
        if (i < VDIM) { d_flag[i] = 0; d_cid[i] = 0; }
        if (i < VPAD) d_used[i] = 0;
        if (i == 0) d_count = 0;
        return;
    }
    int i = blockIdx.x * blockDim.x + threadIdx.x;
    if (i >= CPAD * NPAIR) return;
    int c = i / NPAIR;
    int j = i - c * NPAIR;
    int k0 = 2 * j, k1 = 2 * j + 1;
    float x0 = 0.0f, x1 = 0.0f;
    if (c < CDIM) {
        int row = colmap(c);
        if (k0 < KDIM) x0 = diags[row * KDIM + k0];
        if (k1 < KDIM) x1 = diags[row * KDIM + k1];
    }
    d_Ac[c * NPAIR + pslot(j)] = fp16pack(x0, x1);
}

// ---------------------------------------------------------------------------
// B. mark tokens appearing within doc_lens
// ---------------------------------------------------------------------------
__global__ void mark_kernel(const int* __restrict__ docs,
                            const int* __restrict__ doc_lens) {
    int i = blockIdx.x * blockDim.x + threadIdx.x;
    int b = i >> 9, t = i & (LDIM - 1);
    if (b < BDIM && t < doc_lens[b]) d_flag[docs[i]] = 1;
}

// ---------------------------------------------------------------------------
// C. fused: split_emb (y in [0,10)) + assign (y == 10, x < 79)
// ---------------------------------------------------------------------------
__global__ void prepC_kernel(const float* __restrict__ E) {
    int tx = threadIdx.x, ty = threadIdx.y;   // (32, 8)
    int tid = ty * 32 + tx;

    if (blockIdx.y == (KPAD + 31) / 32) {     // assign row
        if (blockIdx.x >= CL_BLOCKS) return;
        int v = blockIdx.x * 256 + tid;
        if (v >= VDIM) return;
        int lane = tx;
        int f = d_flag[v];
        unsigned mask = __ballot_sync(0xffffffffu, f != 0);
        int base = 0;
        if (lane == 0 && mask) base = atomicAdd(&d_count, __popc(mask));
        base = __shfl_sync(0xffffffffu, base, 0);
        if (f) {
            int cid = base + __popc(mask & ((1u << lane) - 1));
            d_cid[v] = cid;
            d_used[cid] = v;
        }
        return;
    }

    __shared__ float tile[32][33];
    int vt = blockIdx.x * 32;
    int kt = blockIdx.y * 32;
#pragma unroll
    for (int r = 0; r < 4; r++) {
        int k = kt + ty + r * 8, v = vt + tx;
        tile[ty + r * 8][tx] = (k < KDIM && v < VDIM) ? E[(size_t)k * VDIM + v] : 0.0f;
    }
    __syncthreads();
#pragma unroll
    for (int w = 0; w < 2; w++) {
        int idx = tid + 256 * w;               // 0..511 = 32 v x 16 pairs
        int j = idx & 15, vv = idx >> 4;
        int gp = (kt >> 1) + j;
        if (gp >= NPAIR) continue;
        int v = vt + vv;
        if (v >= VDIM || !d_flag[v]) continue;
        d_Bc[(size_t)v * NPAIR + pslot(gp)] =
            fp16pack(tile[2 * j][vv], tile[2 * j + 1][vv]);
    }
}

// ---------------------------------------------------------------------------
// D. GEMM over USED tokens only: D[128 cid x 128 c'] per CTA.
//    Packed hi/lo: one LDS.128 per fragment pair. 12 LDS.128 per chunk.
// ---------------------------------------------------------------------------
#define ROW_BYTES   64                         // 8 uint2 per row per chunk
#define ARR_BYTES   (128 * ROW_BYTES)          // 8192
#define STAGE_BYTES (2 * ARR_BYTES)            // 16384
#define OFF_A 0
#define OFF_B ARR_BYTES
#define TOK_BYTES   512
#define GSMEM_TOTAL (2 * STAGE_BYTES + TOK_BYTES)  // 33280

__global__ void __launch_bounds__(256, 2)
gemm_mma_kernel(const float* __restrict__ bias) {
    extern __shared__ __align__(16) char smem[];
    const uint32_t sb = smem_u32(smem);
    int* s_tok = (int*)(smem + 2 * STAGE_BYTES);

    const int cnt = d_count;
    const int vBase = blockIdx.x * 128;
    if (vBase >= cnt) return;

    const int tid = threadIdx.x;
    const int wid = tid >> 5;
    const int lid = tid & 31;
    const int g   = lid >> 2;
    const int t   = lid & 3;
    const int wm  = (wid & 3) * 32;
    const int wn  = (wid >> 2) * 64;
    const int cBase = blockIdx.y * 128;

    if (tid < 128) {
        int cid = vBase + tid;
        s_tok[tid] = d_used[(cid < cnt) ? cid : 0];
    }
    __syncthreads();

    const uint2* gAc = d_Ac + (size_t)cBase * NPAIR;

    auto load_chunk = [&](int kc, int s) {
        const uint32_t st = sb + s * STAGE_BYTES;
        const int p0 = kc * 8;
        const int r = tid >> 1;                 // 0..127
        const int h = tid & 1;                  // half-row
        const uint32_t so = (uint32_t)r * ROW_BYTES + h * 32;
        size_t gm = (size_t)s_tok[r] * NPAIR + p0 + h * 4;
        cpa16(st + OFF_A + so,      d_Bc + gm);
        cpa16(st + OFF_A + so + 16, d_Bc + gm + 2);
        size_t gn = (size_t)r * NPAIR + p0 + h * 4;
        cpa16(st + OFF_B + so,      gAc + gn);
        cpa16(st + OFF_B + so + 16, gAc + gn + 2);
        CPA_COMMIT();
    };

    float acc[2][8][4];
#pragma unroll
    for (int mi = 0; mi < 2; mi++)
#pragma unroll
        for (int ni = 0; ni < 8; ni++)
#pragma unroll
            for (int e = 0; e < 4; e++) acc[mi][ni][e] = 0.0f;

    load_chunk(0, 0);
    load_chunk(1, 1);

    for (int i = 0; i < NCHUNK; i++) {
        const int s = i & 1;
        if (i + 1 < NCHUNK) { CPA_WAIT1(); } else { CPA_WAIT0(); }
        __syncthreads();

        const char* stg = smem + s * STAGE_BYTES;

        uint32_t Ah[2][4], Al[2][4];
#pragma unroll
        for (int mi = 0; mi < 2; mi++) {
            int r0 = wm + mi * 16 + g;
            float4 f0 = *(const float4*)(stg + OFF_A + r0 * ROW_BYTES + t * 16);
            float4 f1 = *(const float4*)(stg + OFF_A + (r0 + 8) * ROW_BYTES + t * 16);
            Ah[mi][0] = __float_as_uint(f0.x); Al[mi][0] = __float_as_uint(f0.y);
            Ah[mi][2] = __float_as_uint(f0.z); Al[mi][2] = __float_as_uint(f0.w);
            Ah[mi][1] = __float_as_uint(f1.x); Al[mi][1] = __float_as_uint(f1.y);
            Ah[mi][3] = __float_as_uint(f1.z); Al[mi][3] = __float_as_uint(f1.w);
        }
#pragma unroll
        for (int ni = 0; ni < 8; ni++) {
            int rn = wn + ni * 8 + g;
            float4 fb = *(const float4*)(stg + OFF_B + rn * ROW_BYTES + t * 16);
            uint32_t bh0 = __float_as_uint(fb.x), bl0 = __float_as_uint(fb.y);
            uint32_t bh1 = __float_as_uint(fb.z), bl1 = __float_as_uint(fb.w);
#pragma unroll
            for (int mi = 0; mi < 2; mi++) {
                mma16816(acc[mi][ni], Ah[mi][0], Ah[mi][1], Ah[mi][2], Ah[mi][3], bh0, bh1);
                mma16816(acc[mi][ni], Ah[mi][0], Ah[mi][1], Ah[mi][2], Ah[mi][3], bl0, bl1);
                mma16816(acc[mi][ni], Al[mi][0], Al[mi][1], Al[mi][2], Al[mi][3], bh0, bh1);
            }
        }
        __syncthreads();
        if (i + 2 < NCHUNK) load_chunk(i + 2, s);
    }

    // ---- epilogue: +bias, logsig, float2 stores to table[cid][c'] ----
#pragma unroll
    for (int ni = 0; ni < 8; ni++) {
        const int c = cBase + wn + ni * 8 + 2 * t;
        if (c >= CDIM) continue;
        const int c1 = c + 1;
        const float b0 = __ldg(&bias[colmap(c)]);
        const float b1 = (c1 < CDIM) ? __ldg(&bias[colmap(c1)]) : 0.0f;
#pragma unroll
        for (int mi = 0; mi < 2; mi++) {
            const int v0 = vBase + wm + mi * 16 + g;
            const int v1 = v0 + 8;
            if (v0 < cnt) {
                float2 r;
                r.x = logsig(acc[mi][ni][0] + b0);
                r.y = logsig(acc[mi][ni][1] + b1);
                *(float2*)&d_table[(size_t)v0 * TSTR + c] = r;
            }
            if (v1 < cnt) {
                float2 r;
                r.x = logsig(acc[mi][ni][2] + b0);
                r.y = logsig(acc[mi][ni][3] + b1);
                *(float2*)&d_table[(size_t)v1 * TSTR + c] = r;
            }
        }
    }
}

// ---------------------------------------------------------------------------
// E. scan: block (b, q) handles chunks ch=2q and 2q+1, interleaved per
//    thread (2 independent chains). Uniform 36-step loop.
// ---------------------------------------------------------------------------
#define NTS 36

__global__ void __launch_bounds__(160)
scan_part_kernel(const int*   __restrict__ docs,
                 const int*   __restrict__ doc_lens,
                 const float* __restrict__ wildcards) {
    const int b   = blockIdx.x;
    const int q   = blockIdx.y;
    const int tid = threadIdx.x;
    const int p   = tid;
    const bool valid = (p < PDIM);

    const int ch0 = 2 * q, ch1 = 2 * q + 1;
    const int len = doc_lens[b];
    const int c00 = ch0 * SCT, c01 = ch1 * SCT;

    if (len <= c00) {
        if (valid) { d_part[b][ch0][p] = NEGF; d_part[b][ch1][p] = NEGF; }
        return;
    }

    const int ts0 = (c00 >= 4) ? c00 - 4 : 0;
    const int ts1 = c01 - 4;

    __shared__ int tok[2][NTS];
    for (int i = tid; i < 2 * NTS; i += 160) {
        int j = i / NTS, ii = i - j * NTS;
        int ts = j ? ts1 : ts0;
        int gi = ts + ii; if (gi >= LDIM) gi = LDIM - 1;
        tok[j][ii] = d_cid[docs[b * LDIM + gi]];
    }
    __syncthreads();

    const int endSel = p / 50;
    const int off    = (endSel == 0) ? 3 * p
                     : (endSel == 1) ? 4 * p - 50
                                     : 5 * p - 150;

    float wl[5];
#pragma unroll
    for (int m = 0; m < 5; m++)
        wl[m] = valid ? logsig(__ldg(&wildcards[p * 5 + m])) : 0.0f;

    float ha[2][5], sc[2];
    float pf[2][4][5];
#pragma unroll
    for (int j = 0; j < 2; j++) {
        sc[j] = NEGF;
#pragma unroll
        for (int m = 0; m < 5; m++) ha[j][m] = NEGF;
#pragma unroll
        for (int u = 0; u < 4; u++) {
            if (valid) {
                const float* row = &d_table[(size_t)tok[j][u] * TSTR + off];
#pragma unroll
                for (int m = 0; m < 5; m++) pf[j][u][m] = __ldg(&row[m]);
            } else {
#pragma unroll
                for (int m = 0; m < 5; m++) pf[j][u][m] = 0.0f;
            }
        }
    }

    const int lo0 = c00 - ts0;
    const int hi0 = (len < c00 + SCT ? len : c00 + SCT) - ts0;
    const int lo1 = 4;
    const int hi1 = (len < c01 + SCT ? len : c01 + SCT) - ts1;

    for (int i = 0; i < NTS; i += 4) {
#pragma unroll
        for (int u = 0; u < 4; u++) {
            const int li = i + u;
            const int ni = li + 4;
#pragma unroll
            for (int j = 0; j < 2; j++) {
                float e0 = fmaxf(pf[j][u][0], wl[0]);
                float e1 = fmaxf(pf[j][u][1], wl[1]);
                float e2 = fmaxf(pf[j][u][2], wl[2]);
                float e3 = fmaxf(pf[j][u][3], wl[3]);
                float e4 = fmaxf(pf[j][u][4], wl[4]);
                ha[j][4] = ha[j][3] + e4;
                ha[j][3] = ha[j][2] + e3;
                ha[j][2] = ha[j][1] + e2;
                ha[j][1] = ha[j][0] + e1;
                ha[j][0] = e0;
                float ev = (endSel == 0) ? ha[j][2]
                         : (endSel == 1) ? ha[j][3] : ha[j][4];
                const int lo = j ? lo1 : lo0;
                const int hi = j ? hi1 : hi0;
                sc[j] = (li >= lo && li < hi) ? fmaxf(sc[j], ev) : sc[j];
                if (ni < NTS && valid) {
                    const float* row = &d_table[(size_t)tok[j][ni] * TSTR + off];
#pragma unroll
                    for (int m = 0; m < 5; m++) pf[j][u][m] = __ldg(&row[m]);
                }
            }
        }
    }

    if (valid) {
        d_part[b][ch0][p] = sc[0];
        d_part[b][ch1][p] = sc[1];
    }
}

// ---------------------------------------------------------------------------
// F. final: reduce chunks, exp/LN/heaviside/linear
// ---------------------------------------------------------------------------
__global__ void __launch_bounds__(160)
scan_final_kernel(const float* __restrict__ gamma,
                  const float* __restrict__ beta,
                  const float* __restrict__ W,
                  const float* __restrict__ lb,
                  float*       __restrict__ out) {
    const int b   = blockIdx.x;
    const int tid = threadIdx.x;
    const bool valid = (tid < PDIM);

    __shared__ float sh[192];
    __shared__ float sred[2];

    float sc = NEGF;
    if (valid) {
#pragma unroll
        for (int ch = 0; ch < NSC; ch++) sc = fmaxf(sc, d_part[b][ch][tid]);
    }
    float score = valid ? expf(sc) : 0.0f;

    sh[tid] = score;
    __syncthreads();
    if (tid < 32) {
        float s = 0.0f;
        for (int i = tid; i < PDIM; i += 32) s += sh[i];
#pragma unroll
        for (int o = 16; o > 0; o >>= 1) s += __shfl_down_sync(0xffffffffu, s, o);
        if (tid == 0) sred[0] = s * (1.0f / PDIM);
    }
    __syncthreads();
    const float mu = sred[0];

    float d = score - mu;
    sh[tid] = valid ? d * d : 0.0f;
    __syncthreads();
    if (tid < 32) {
        float s = 0.0f;
        for (int i = tid; i < PDIM; i += 32) s += sh[i];
#pragma unroll
        for (int o = 16; o > 0; o >>= 1) s += __shfl_down_sync(0xffffffffu, s, o);
        if (tid == 0) sred[1] = s * (1.0f / PDIM);
    }
    __syncthreads();
    const float var = sred[1];

    float bin = 0.0f;
    if (valid) {
        float norm = (score - mu) * rsqrtf(var + 1e-5f) * __ldg(&gamma[tid]) + __ldg(&beta[tid]);
        bin = (norm > 0.0f) ? 1.0f : 0.0f;
    }

    sh[tid] = valid ? bin * __ldg(&W[tid]) : 0.0f;
    __syncthreads();
    if (tid < 32) {
        float s = 0.0f;
        for (int i = tid; i < PDIM; i += 32) s += sh[i];
#pragma unroll
        for (int o = 16; o > 0; o >>= 1) s += __shfl_down_sync(0xffffffffu, s, o);
        if (tid == 0) out[b * 2 + 0] = s + __ldg(&lb[0]);
    }
    __syncthreads();
    sh[tid] = valid ? bin * __ldg(&W[PDIM + tid]) : 0.0f;
    __syncthreads();
    if (tid < 32) {
        float s = 0.0f;
        for (int i = tid; i < PDIM; i += 32) s += sh[i];
#pragma unroll
        for (int o = 16; o > 0; o >>= 1) s += __shfl_down_sync(0xffffffffu, s, o);
        if (tid == 0) out[b * 2 + 1] = s + __ldg(&lb[1]);
    }
}

// ---------------------------------------------------------------------------
// launch
// ---------------------------------------------------------------------------
extern "C" void kernel_launch(void* const* d_in, const int* in_sizes, int n_in,
                              void* d_out, int out_size) {
    const int*   docs      = (const int*)  d_in[0];
    const int*   doc_lens  = (const int*)  d_in[1];
    const float* emb       = (const float*)d_in[2];
    const float* diags     = (const float*)d_in[3];
    const float* bias      = (const float*)d_in[4];
    const float* wildcards = (const float*)d_in[5];
    const float* ln_gamma  = (const float*)d_in[6];
    const float* ln_beta   = (const float*)d_in[7];
    const float* linear_w  = (const float*)d_in[8];
    const float* linear_b  = (const float*)d_in[9];
    float*       out       = (float*)d_out;

    (void)in_sizes; (void)n_in; (void)out_size;

    cudaFuncSetAttribute(gemm_mma_kernel,
                         cudaFuncAttributeMaxDynamicSharedMemorySize, GSMEM_TOTAL);

    prepA_kernel<<<SD_BLOCKS + CL_BLOCKS, 256>>>(diags);
    mark_kernel<<<(BDIM * LDIM + 255) / 256, 256>>>(docs, doc_lens);

    dim3 cgrid((VPAD + 31) / 32, (KPAD + 31) / 32 + 1);   // (628, 11)
    prepC_kernel<<<cgrid, dim3(32, 8)>>>(emb);

    dim3 ggrid(VPAD / 128, CPAD / 128);                   // (157, 5)
    gemm_mma_kernel<<<ggrid, 256, GSMEM_TOTAL>>>(bias);

    dim3 sgrid(BDIM, NSC / 2);                            // (64, 8)
    scan_part_kernel<<<sgrid, 160>>>(docs, doc_lens, wildcards);

    scan_final_kernel<<<BDIM, 160>>>(ln_gamma, ln_beta, linear_w, linear_b, out);
}